// round 10
// baseline (speedup 1.0000x reference)
#include <cuda_runtime.h>
#include <cuda_bf16.h>
#include <cstdint>

// Problem constants (fixed by the dataset reference):
//   feature        [32,512,512] f32      -> P = 8,388,608 points
//   indices        [32,512,512,3] i32    -> 3P ints
//   feature_volume [256,256,256] f32     -> V = 16,777,216 voxels
//   count_volume   [256,256,256] f32
//   output: concat(feature_volume', count_volume') -> 2V f32
#define DIM      256
#define V_TOTAL  (DIM * DIM * DIM)

// Bucketing: bucket = flat >> 12 (4096 voxels per bucket, one SMEM slab).
#define NBUCKET  4096
#define SLAB     4096            // voxels per bucket = CTA slab
#define CAP      4096            // entries per bucket (2x the 2048 mean;
                                 // binomial overflow prob ~e^-700, guarded)

// Per-bucket point lists: entry = (feat_bits << 32) | local_voxel_offset.
// 4096 * 4096 * 8B = 134 MB zero-init device global (same footprint as the
// scratch array every prior passing round used). Counters reset per replay.
__device__ unsigned long long g_bucket[(size_t)NBUCKET * CAP];
__device__ int                g_count[NBUCKET];

// ---------------------------------------------------------------------------
// Reset bucket counters (graph-replayed prologue).
// ---------------------------------------------------------------------------
__global__ void __launch_bounds__(256) ctr_zero_kernel()
{
    const int t = blockIdx.x * blockDim.x + threadIdx.x;
    if (t < NBUCKET) g_count[t] = 0;
}

// ---------------------------------------------------------------------------
// Bin: one streaming pass over all points. 4 points/thread, vectorized
// loads (__ldcs, evict-first). Per valid point: reserve a slot in its
// bucket via atomicAdd on the bucket counter, then store the packed entry.
// ---------------------------------------------------------------------------
__global__ void __launch_bounds__(256) bin_kernel(
    const float* __restrict__ feat,
    const int*   __restrict__ idx,
    int P4)
{
    const int t = blockIdx.x * blockDim.x + threadIdx.x;
    if (t >= P4) return;

    const float4 f  = __ldcs(reinterpret_cast<const float4*>(feat) + t);
    const int4   i0 = __ldcs(reinterpret_cast<const int4*>(idx) + t * 3 + 0);
    const int4   i1 = __ldcs(reinterpret_cast<const int4*>(idx) + t * 3 + 1);
    const int4   i2 = __ldcs(reinterpret_cast<const int4*>(idx) + t * 3 + 2);

    const int xs[4] = { i0.x, i0.w, i1.z, i2.y };
    const int ys[4] = { i0.y, i1.x, i1.w, i2.z };
    const int zs[4] = { i0.z, i1.y, i2.x, i2.w };
    const float fv[4] = { f.x, f.y, f.z, f.w };

#pragma unroll
    for (int k = 0; k < 4; ++k) {
        const int x = xs[k], y = ys[k], z = zs[k];
        const bool valid = ((unsigned)x < (unsigned)DIM) &
                           ((unsigned)y < (unsigned)DIM) &
                           ((unsigned)z < (unsigned)DIM);
        if (valid) {
            const int flat = (((x << 8) | y) << 8) | z;
            const int b    = flat >> 12;           // bucket
            const unsigned loc = (unsigned)(flat & (SLAB - 1));
            const int slot = atomicAdd(&g_count[b], 1);
            if (slot < CAP) {
                const unsigned long long e =
                    ((unsigned long long)__float_as_uint(fv[k]) << 32) | loc;
                __stcs(&g_bucket[(size_t)b * CAP + slot], e);
            }
        }
    }
}

// ---------------------------------------------------------------------------
// Process: CTA k owns voxel slab [k*SLAB, (k+1)*SLAB). Accumulators live
// entirely in SMEM (32 KB static). Replay the bucket with SMEM atomics
// (spread-address ATOMS), then finalize:
//   touched  : fv' = fv*cc + (sum/cnt)/(cc+1) ; cv' = cc+1
//   untouched: fv' = fv ; cv' = cc
// All gmem traffic in this kernel is fully coalesced float4.
// ---------------------------------------------------------------------------
__global__ void __launch_bounds__(256) process_kernel(
    const float* __restrict__ fvol,
    const float* __restrict__ cvol,
    float*       __restrict__ out)
{
    __shared__ float2 acc[SLAB];                 // 32 KB

    const int k   = blockIdx.x;
    const int tid = threadIdx.x;

    // Zero the slab accumulators.
    float4* a4 = reinterpret_cast<float4*>(acc); // SLAB/2 = 2048 float4
    for (int i = tid; i < SLAB / 2; i += 256)
        a4[i] = make_float4(0.f, 0.f, 0.f, 0.f);
    __syncthreads();

    // Replay this bucket's points into SMEM.
    int c = g_count[k];
    if (c > CAP) c = CAP;
    const unsigned long long* bk = g_bucket + (size_t)k * CAP;
    for (int i = tid; i < c; i += 256) {
        const unsigned long long e = __ldcs(bk + i);
        const unsigned loc = (unsigned)(e & (SLAB - 1));
        const float    fv  = __uint_as_float((unsigned)(e >> 32));
        atomicAdd(&acc[loc].x, fv);
        atomicAdd(&acc[loc].y, 1.0f);
    }
    __syncthreads();

    // Finalize the slab: coalesced float4 in/out.
    const long base = (long)k * SLAB;
    const float4* fv4 = reinterpret_cast<const float4*>(fvol + base);
    const float4* cv4 = reinterpret_cast<const float4*>(cvol + base);
    float4* of4 = reinterpret_cast<float4*>(out + base);
    float4* oc4 = reinterpret_cast<float4*>(out + V_TOTAL + base);

    for (int i = tid; i < SLAB / 4; i += 256) {  // 1024 groups, 4 iters
        const float4 a = __ldcs(fv4 + i);
        const float4 cvv = __ldcs(cv4 + i);
        const float2 s0 = acc[4 * i + 0];
        const float2 s1 = acc[4 * i + 1];
        const float2 s2 = acc[4 * i + 2];
        const float2 s3 = acc[4 * i + 3];

        const float sum[4] = { s0.x, s1.x, s2.x, s3.x };
        const float cnt[4] = { s0.y, s1.y, s2.y, s3.y };
        const float fa[4]  = { a.x, a.y, a.z, a.w };
        const float cc[4]  = { cvv.x, cvv.y, cvv.z, cvv.w };

        float of[4], oc[4];
#pragma unroll
        for (int j = 0; j < 4; ++j) {
            if (cnt[j] > 0.0f) {
                const float cn = cc[j] + 1.0f;
                of[j] = fa[j] * cc[j] + (sum[j] / cnt[j]) / cn;
                oc[j] = cn;
            } else {
                of[j] = fa[j];
                oc[j] = cc[j];
            }
        }

        __stcs(of4 + i, make_float4(of[0], of[1], of[2], of[3]));
        __stcs(oc4 + i, make_float4(oc[0], oc[1], oc[2], oc[3]));
    }
}

extern "C" void kernel_launch(void* const* d_in, const int* in_sizes, int n_in,
                              void* d_out, int out_size)
{
    const float* feat = (const float*)d_in[0];   // [P]
    const int*   idx  = (const int*)d_in[1];     // [P,3]
    const float* fvol = (const float*)d_in[2];   // [V]
    const float* cvol = (const float*)d_in[3];   // [V]
    float*       out  = (float*)d_out;           // [2V]

    const int P  = in_sizes[0];                  // 8,388,608 (divisible by 4)
    const int P4 = (P + 3) / 4;

    ctr_zero_kernel<<<(NBUCKET + 255) / 256, 256>>>();
    bin_kernel<<<(P4 + 255) / 256, 256>>>(feat, idx, P4);
    process_kernel<<<NBUCKET, 256>>>(fvol, cvol, out);
}